// round 14
// baseline (speedup 1.0000x reference)
#include <cuda_runtime.h>
#include <cstdint>
#include <cstring>

#define MAXN 100000
#define MAXE 1600000
#define DIM  128
#define CAP  64     // bucket capacity (Poisson(16): P(>=64) ~ 1e-30)
#define APAD 132    // A-tile smem stride: fragment banks 4*lr+lc, conflict-free
#define WPAD 136    // W smem stride: fragment banks 8*lc+lr, conflict-free

// ---------------- device scratch (no allocations allowed) -------------------
__device__ float    g_agg[(size_t)MAXN * DIM];  // aggregated feats, tf32 bits
__device__ int      g_cnt[MAXN];
__device__ int      g_bkt[(size_t)MAXN * CAP];  // per-dst source lists
__device__ float    g_dinv[MAXN];               // deg^-1/2 lookup
__device__ uint4    g_mask[MAXN];               // 128-bit dropout keep mask
__device__ uint32_t g_wtf[DIM * DIM];           // W pre-converted to tf32

// ---------------------------------------------------------------------------
// threefry2x32, JAX partitionable path (validated R1-R11)
// ---------------------------------------------------------------------------
__device__ __forceinline__ uint32_t rotl32(uint32_t v, int s) {
    return (v << s) | (v >> (32 - s));
}
__device__ __forceinline__ uint32_t threefry_bits(uint32_t ctr) {
    const uint32_t ks0 = 0u;
    const uint32_t ks1 = 42u;
    const uint32_t ks2 = 0u ^ 42u ^ 0x1BD11BDAu;
    uint32_t x0 = 0u + ks0;
    uint32_t x1 = ctr + ks1;
#define TFR(r) { x0 += x1; x1 = rotl32(x1, r); x1 ^= x0; }
    TFR(13) TFR(15) TFR(26) TFR(6)
    x0 += ks1; x1 += ks2 + 1u;
    TFR(17) TFR(29) TFR(16) TFR(24)
    x0 += ks2; x1 += ks0 + 2u;
    TFR(13) TFR(15) TFR(26) TFR(6)
    x0 += ks0; x1 += ks1 + 3u;
    TFR(17) TFR(29) TFR(16) TFR(24)
    x0 += ks1; x1 += ks2 + 4u;
    TFR(13) TFR(15) TFR(26) TFR(6)
    x0 += ks2; x1 += ks0 + 5u;
#undef TFR
    return x0 ^ x1;
}

__device__ __forceinline__ float f2tf32f(float f) {
    uint32_t r;
    asm("cvt.rna.tf32.f32 %0, %1;" : "=r"(r) : "f"(f));
    return __uint_as_float(r);
}

__device__ __forceinline__ void mma_tf32(float* c, const uint32_t* a, const uint32_t* b) {
    asm volatile(
        "mma.sync.aligned.m16n8k8.row.col.f32.tf32.tf32.f32 "
        "{%0,%1,%2,%3}, {%4,%5,%6,%7}, {%8,%9}, {%0,%1,%2,%3};"
        : "+f"(c[0]), "+f"(c[1]), "+f"(c[2]), "+f"(c[3])
        : "r"(a[0]), "r"(a[1]), "r"(a[2]), "r"(a[3]), "r"(b[0]), "r"(b[1]));
}

// ---------------------------------------------------------------------------
// K1: zero counts
// ---------------------------------------------------------------------------
__global__ void k_init(int n4) {
    int i = blockIdx.x * blockDim.x + threadIdx.x;
    if (i < n4) ((int4*)g_cnt)[i] = make_int4(0, 0, 0, 0);
}

// K1b: W -> tf32 (one-shot, 16 blocks)
__global__ void k_wconv(const float* __restrict__ w) {
    int i = (blockIdx.x * blockDim.x + threadIdx.x) * 4;
    float4 v = *(const float4*)&w[i];
    g_wtf[i + 0] = __float_as_uint(f2tf32f(v.x));
    g_wtf[i + 1] = __float_as_uint(f2tf32f(v.y));
    g_wtf[i + 2] = __float_as_uint(f2tf32f(v.z));
    g_wtf[i + 3] = __float_as_uint(f2tf32f(v.w));
}

// K2: bucket fill — 4 edges per thread (latency-bound, deep MLP)
__global__ __launch_bounds__(256)
void k_fill(const int* __restrict__ src, const int* __restrict__ dst, int e4) {
    int i = blockIdx.x * blockDim.x + threadIdx.x;
    if (i >= e4) return;
    int4 d = ((const int4*)dst)[i];
    int4 s = ((const int4*)src)[i];
    int p0 = atomicAdd(&g_cnt[d.x], 1);
    int p1 = atomicAdd(&g_cnt[d.y], 1);
    int p2 = atomicAdd(&g_cnt[d.z], 1);
    int p3 = atomicAdd(&g_cnt[d.w], 1);
    if (p0 < CAP) g_bkt[(size_t)d.x * CAP + p0] = s.x;
    if (p1 < CAP) g_bkt[(size_t)d.y * CAP + p1] = s.y;
    if (p2 < CAP) g_bkt[(size_t)d.z * CAP + p2] = s.z;
    if (p3 < CAP) g_bkt[(size_t)d.w * CAP + p3] = s.w;
}

// K2b: dinv lookup table (counts final after k_fill)
__global__ void k_dinv(int n) {
    int i = blockIdx.x * blockDim.x + threadIdx.x;
    if (i < n) g_dinv[i] = rsqrtf((float)g_cnt[i] + 1.0f);
}

// ---------------------------------------------------------------------------
// K3: Gather-aggregate + dropout-mask gen + tf32 convert. One warp per node.
// NO shuffles (R11 lesson: gather was SHFL/issue-bound, not L2-bound).
// Edge indices read via warp-uniform int4 LDG (1 wavefront), neighbor norms
// via warp-uniform g_dinv lookup.
// ---------------------------------------------------------------------------
__global__ __launch_bounds__(256)
void k_gather(const float* __restrict__ x, int n) {
    int wid  = blockIdx.x * 8 + (threadIdx.x >> 5);
    int lane = threadIdx.x & 31;
    if (wid >= n) return;

    int c = g_cnt[wid];
    if (c > CAP) c = CAP;
    float dv = g_dinv[wid];

    float4 acc = *(const float4*)&x[(size_t)wid * DIM + lane * 4];
    acc.x *= dv; acc.y *= dv; acc.z *= dv; acc.w *= dv;

    uint32_t bctr = (uint32_t)wid * DIM + lane;
    uint32_t m0 = __ballot_sync(0xffffffffu, !(threefry_bits(bctr +  0) >> 31));
    uint32_t m1 = __ballot_sync(0xffffffffu, !(threefry_bits(bctr + 32) >> 31));
    uint32_t m2 = __ballot_sync(0xffffffffu, !(threefry_bits(bctr + 64) >> 31));
    uint32_t m3 = __ballot_sync(0xffffffffu, !(threefry_bits(bctr + 96) >> 31));
    if (lane == 0) g_mask[wid] = make_uint4(m0, m1, m2, m3);

    const int* bkt = &g_bkt[(size_t)wid * CAP];
    const float* xl = x + lane * 4;
    int j = 0;
    for (; j + 8 <= c; j += 8) {
        int4 i0 = *(const int4*)&bkt[j];        // warp-uniform broadcast LDG
        int4 i1 = *(const int4*)&bkt[j + 4];
        float d0 = g_dinv[i0.x], d1 = g_dinv[i0.y];
        float d2 = g_dinv[i0.z], d3 = g_dinv[i0.w];
        float d4 = g_dinv[i1.x], d5 = g_dinv[i1.y];
        float d6 = g_dinv[i1.z], d7 = g_dinv[i1.w];
        float4 a0 = *(const float4*)&xl[(size_t)i0.x * DIM];
        float4 a1 = *(const float4*)&xl[(size_t)i0.y * DIM];
        float4 a2 = *(const float4*)&xl[(size_t)i0.z * DIM];
        float4 a3 = *(const float4*)&xl[(size_t)i0.w * DIM];
        float4 a4 = *(const float4*)&xl[(size_t)i1.x * DIM];
        float4 a5 = *(const float4*)&xl[(size_t)i1.y * DIM];
        float4 a6 = *(const float4*)&xl[(size_t)i1.z * DIM];
        float4 a7 = *(const float4*)&xl[(size_t)i1.w * DIM];
        acc.x = fmaf(d0, a0.x, acc.x); acc.y = fmaf(d0, a0.y, acc.y);
        acc.z = fmaf(d0, a0.z, acc.z); acc.w = fmaf(d0, a0.w, acc.w);
        acc.x = fmaf(d1, a1.x, acc.x); acc.y = fmaf(d1, a1.y, acc.y);
        acc.z = fmaf(d1, a1.z, acc.z); acc.w = fmaf(d1, a1.w, acc.w);
        acc.x = fmaf(d2, a2.x, acc.x); acc.y = fmaf(d2, a2.y, acc.y);
        acc.z = fmaf(d2, a2.z, acc.z); acc.w = fmaf(d2, a2.w, acc.w);
        acc.x = fmaf(d3, a3.x, acc.x); acc.y = fmaf(d3, a3.y, acc.y);
        acc.z = fmaf(d3, a3.z, acc.z); acc.w = fmaf(d3, a3.w, acc.w);
        acc.x = fmaf(d4, a4.x, acc.x); acc.y = fmaf(d4, a4.y, acc.y);
        acc.z = fmaf(d4, a4.z, acc.z); acc.w = fmaf(d4, a4.w, acc.w);
        acc.x = fmaf(d5, a5.x, acc.x); acc.y = fmaf(d5, a5.y, acc.y);
        acc.z = fmaf(d5, a5.z, acc.z); acc.w = fmaf(d5, a5.w, acc.w);
        acc.x = fmaf(d6, a6.x, acc.x); acc.y = fmaf(d6, a6.y, acc.y);
        acc.z = fmaf(d6, a6.z, acc.z); acc.w = fmaf(d6, a6.w, acc.w);
        acc.x = fmaf(d7, a7.x, acc.x); acc.y = fmaf(d7, a7.y, acc.y);
        acc.z = fmaf(d7, a7.z, acc.z); acc.w = fmaf(d7, a7.w, acc.w);
    }
    for (; j + 4 <= c; j += 4) {
        int4 i0 = *(const int4*)&bkt[j];
        float d0 = g_dinv[i0.x], d1 = g_dinv[i0.y];
        float d2 = g_dinv[i0.z], d3 = g_dinv[i0.w];
        float4 a0 = *(const float4*)&xl[(size_t)i0.x * DIM];
        float4 a1 = *(const float4*)&xl[(size_t)i0.y * DIM];
        float4 a2 = *(const float4*)&xl[(size_t)i0.z * DIM];
        float4 a3 = *(const float4*)&xl[(size_t)i0.w * DIM];
        acc.x = fmaf(d0, a0.x, acc.x); acc.y = fmaf(d0, a0.y, acc.y);
        acc.z = fmaf(d0, a0.z, acc.z); acc.w = fmaf(d0, a0.w, acc.w);
        acc.x = fmaf(d1, a1.x, acc.x); acc.y = fmaf(d1, a1.y, acc.y);
        acc.z = fmaf(d1, a1.z, acc.z); acc.w = fmaf(d1, a1.w, acc.w);
        acc.x = fmaf(d2, a2.x, acc.x); acc.y = fmaf(d2, a2.y, acc.y);
        acc.z = fmaf(d2, a2.z, acc.z); acc.w = fmaf(d2, a2.w, acc.w);
        acc.x = fmaf(d3, a3.x, acc.x); acc.y = fmaf(d3, a3.y, acc.y);
        acc.z = fmaf(d3, a3.z, acc.z); acc.w = fmaf(d3, a3.w, acc.w);
    }
    for (; j < c; j++) {
        int s = bkt[j];
        float dd = g_dinv[s];
        float4 a = *(const float4*)&xl[(size_t)s * DIM];
        acc.x = fmaf(dd, a.x, acc.x); acc.y = fmaf(dd, a.y, acc.y);
        acc.z = fmaf(dd, a.z, acc.z); acc.w = fmaf(dd, a.w, acc.w);
    }
    acc.x = f2tf32f(acc.x * dv); acc.y = f2tf32f(acc.y * dv);
    acc.z = f2tf32f(acc.z * dv); acc.w = f2tf32f(acc.w * dv);
    *(float4*)&g_agg[(size_t)wid * DIM + lane * 4] = acc;
}

// ---------------------------------------------------------------------------
// K4: tf32 tensor-core GEMM + bias + ReLU + dropout. (R8-proven layout)
// CTA = 64 rows x 128 cols, 8 warps (4x2), warp = 16 rows x 64 cols.
// Conflict-free fragment reads; smem 101KB -> 2 CTAs/SM.
// ---------------------------------------------------------------------------
__global__ __launch_bounds__(256, 2)
void k_gemm(const float* __restrict__ bias, float* __restrict__ out, int n)
{
    extern __shared__ uint32_t sm_u[];
    uint32_t* As = sm_u;                       // [64][APAD]
    uint32_t* Ws = sm_u + 64 * APAD;           // [128][WPAD]

    const int tid  = threadIdx.x;
    const int lane = tid & 31;
    const int wrp  = tid >> 5;
    const int base = blockIdx.x * 64;

#pragma unroll
    for (int t = 0; t < 8; t++) {
        int f = (tid + t * 256) * 4;
        int r = f >> 7, c = f & 127;
        int gr = min(base + r, n - 1);
        float4 v = *(const float4*)&g_agg[(size_t)gr * DIM + c];
        *(float4*)&As[r * APAD + c] = *(float4*)&v;
    }
#pragma unroll
    for (int t = 0; t < 16; t++) {
        int f = (tid + t * 256) * 4;
        int k = f >> 7, c = f & 127;
        float4 v = *(const float4*)&g_wtf[f];
        *(float4*)&Ws[k * WPAD + c] = v;
    }
    __syncthreads();

    const int mrow0 = (wrp >> 1) * 16;
    const int ncol0 = (wrp & 1) * 64;
    const int lr = lane >> 2;
    const int lc = lane & 3;

    float acc[8][4];
#pragma unroll
    for (int nt = 0; nt < 8; nt++)
#pragma unroll
        for (int q = 0; q < 4; q++) acc[nt][q] = 0.0f;

#pragma unroll
    for (int k0 = 0; k0 < 128; k0 += 8) {
        uint32_t a[4];
        int r = mrow0 + lr;
        a[0] = As[r * APAD + k0 + lc];
        a[1] = As[(r + 8) * APAD + k0 + lc];
        a[2] = As[r * APAD + k0 + 4 + lc];
        a[3] = As[(r + 8) * APAD + k0 + 4 + lc];
        uint32_t b[8][2];
#pragma unroll
        for (int nt = 0; nt < 8; nt++) {
            int nn = ncol0 + nt * 8 + lr;
            b[nt][0] = Ws[(k0 + lc) * WPAD + nn];
            b[nt][1] = Ws[(k0 + 4 + lc) * WPAD + nn];
        }
#pragma unroll
        for (int nt = 0; nt < 8; nt++)
            mma_tf32(acc[nt], a, b[nt]);
    }

    int r0 = base + mrow0 + lr;
    int r1 = r0 + 8;
    uint4 mk0 = (r0 < n) ? g_mask[r0] : make_uint4(0, 0, 0, 0);
    uint4 mk1 = (r1 < n) ? g_mask[r1] : make_uint4(0, 0, 0, 0);
#pragma unroll
    for (int nt = 0; nt < 8; nt++) {
        int c = ncol0 + nt * 8 + 2 * lc;
        float b0 = bias[c], b1 = bias[c + 1];
        int ws = c >> 5, sh = c & 31;
        uint32_t w0 = (ws == 0) ? mk0.x : (ws == 1) ? mk0.y : (ws == 2) ? mk0.z : mk0.w;
        uint32_t w1 = (ws == 0) ? mk1.x : (ws == 1) ? mk1.y : (ws == 2) ? mk1.z : mk1.w;
        float* cc = acc[nt];
        if (r0 < n) {
            float v0 = fmaxf(cc[0] + b0, 0.0f) * 2.0f;
            float v1 = fmaxf(cc[1] + b1, 0.0f) * 2.0f;
            v0 = ((w0 >> sh) & 1u) ? v0 : 0.0f;
            v1 = ((w0 >> (sh + 1)) & 1u) ? v1 : 0.0f;
            *(float2*)&out[(size_t)r0 * DIM + c] = make_float2(v0, v1);
        }
        if (r1 < n) {
            float v2 = fmaxf(cc[2] + b0, 0.0f) * 2.0f;
            float v3 = fmaxf(cc[3] + b1, 0.0f) * 2.0f;
            v2 = ((w1 >> sh) & 1u) ? v2 : 0.0f;
            v3 = ((w1 >> (sh + 1)) & 1u) ? v3 : 0.0f;
            *(float2*)&out[(size_t)r1 * DIM + c] = make_float2(v2, v3);
        }
    }
}

// ---------------------------------------------------------------------------
extern "C" void kernel_launch(void* const* d_in, const int* in_sizes, int n_in,
                              void* d_out, int out_size)
{
    const float* x    = (const float*)d_in[0];
    const int*   ei   = (const int*)  d_in[1];
    const float* w    = (const float*)d_in[2];
    const float* bias = (const float*)d_in[3];
    float* out = (float*)d_out;

    int n = in_sizes[0] / DIM;      // 100000
    int e = in_sizes[1] / 2;        // 1600000
    const int* srcp = ei;
    const int* dstp = ei + e;

    int n4 = (n + 3) / 4;
    int e4 = e / 4;

    const int smem_bytes = (64 * APAD + DIM * WPAD) * 4;   // 103424 B
    static bool attr_set = false;
    if (!attr_set) {
        cudaFuncSetAttribute(k_gemm, cudaFuncAttributeMaxDynamicSharedMemorySize,
                             smem_bytes);
        attr_set = true;
    }

    k_init <<<(n4 + 255) / 256, 256>>>(n4);
    k_wconv<<<16, 256>>>(w);
    k_fill <<<(e4 + 255) / 256, 256>>>(srcp, dstp, e4);
    k_dinv <<<(n + 255) / 256, 256>>>(n);
    k_gather<<<(n + 7) / 8, 256>>>(x, n);
    k_gemm <<<(n + 63) / 64, 256, smem_bytes>>>(bias, out, n);
}

// round 15
// speedup vs baseline: 1.3968x; 1.3968x over previous
#include <cuda_runtime.h>
#include <cstdint>
#include <cstring>

#define MAXN 100000
#define MAXE 1600000
#define DIM  128
#define CAP  64     // bucket capacity (Poisson(16): P(>=64) ~ 1e-30)
#define APAD 132    // A-tile smem stride: fragment banks 4*lr+lc, conflict-free
#define WPAD 136    // W smem stride: fragment banks 8*lc+lr, conflict-free

// ---------------- device scratch (no allocations allowed) -------------------
__device__ float    g_agg[(size_t)MAXN * DIM];  // aggregated feats, tf32 bits
__device__ int      g_cnt[MAXN];
__device__ int      g_bkt[(size_t)MAXN * CAP];  // per-dst source lists
__device__ float    g_dinv[MAXN];               // deg^-1/2 lookup
__device__ uint4    g_mask[MAXN];               // 128-bit dropout keep mask
__device__ uint32_t g_wtf[DIM * DIM];           // W pre-converted to tf32

// ---------------------------------------------------------------------------
// threefry2x32, JAX partitionable path (validated R1-R11)
// ---------------------------------------------------------------------------
__device__ __forceinline__ uint32_t rotl32(uint32_t v, int s) {
    return (v << s) | (v >> (32 - s));
}
__device__ __forceinline__ uint32_t threefry_bits(uint32_t ctr) {
    const uint32_t ks0 = 0u;
    const uint32_t ks1 = 42u;
    const uint32_t ks2 = 0u ^ 42u ^ 0x1BD11BDAu;
    uint32_t x0 = 0u + ks0;
    uint32_t x1 = ctr + ks1;
#define TFR(r) { x0 += x1; x1 = rotl32(x1, r); x1 ^= x0; }
    TFR(13) TFR(15) TFR(26) TFR(6)
    x0 += ks1; x1 += ks2 + 1u;
    TFR(17) TFR(29) TFR(16) TFR(24)
    x0 += ks2; x1 += ks0 + 2u;
    TFR(13) TFR(15) TFR(26) TFR(6)
    x0 += ks0; x1 += ks1 + 3u;
    TFR(17) TFR(29) TFR(16) TFR(24)
    x0 += ks1; x1 += ks2 + 4u;
    TFR(13) TFR(15) TFR(26) TFR(6)
    x0 += ks2; x1 += ks0 + 5u;
#undef TFR
    return x0 ^ x1;
}

__device__ __forceinline__ float f2tf32f(float f) {
    uint32_t r;
    asm("cvt.rna.tf32.f32 %0, %1;" : "=r"(r) : "f"(f));
    return __uint_as_float(r);
}

__device__ __forceinline__ void mma_tf32(float* c, const uint32_t* a, const uint32_t* b) {
    asm volatile(
        "mma.sync.aligned.m16n8k8.row.col.f32.tf32.tf32.f32 "
        "{%0,%1,%2,%3}, {%4,%5,%6,%7}, {%8,%9}, {%0,%1,%2,%3};"
        : "+f"(c[0]), "+f"(c[1]), "+f"(c[2]), "+f"(c[3])
        : "r"(a[0]), "r"(a[1]), "r"(a[2]), "r"(a[3]), "r"(b[0]), "r"(b[1]));
}

// ---------------------------------------------------------------------------
// K1: zero counts
// ---------------------------------------------------------------------------
__global__ void k_init(int n4) {
    int i = blockIdx.x * blockDim.x + threadIdx.x;
    if (i < n4) ((int4*)g_cnt)[i] = make_int4(0, 0, 0, 0);
}

// K1b: W -> tf32 (one-shot, 16 blocks)
__global__ void k_wconv(const float* __restrict__ w) {
    int i = (blockIdx.x * blockDim.x + threadIdx.x) * 4;
    float4 v = *(const float4*)&w[i];
    g_wtf[i + 0] = __float_as_uint(f2tf32f(v.x));
    g_wtf[i + 1] = __float_as_uint(f2tf32f(v.y));
    g_wtf[i + 2] = __float_as_uint(f2tf32f(v.z));
    g_wtf[i + 3] = __float_as_uint(f2tf32f(v.w));
}

// K2: bucket fill — 4 edges per thread (latency-bound, deep MLP)
__global__ __launch_bounds__(256)
void k_fill(const int* __restrict__ src, const int* __restrict__ dst, int e4) {
    int i = blockIdx.x * blockDim.x + threadIdx.x;
    if (i >= e4) return;
    int4 d = ((const int4*)dst)[i];
    int4 s = ((const int4*)src)[i];
    int p0 = atomicAdd(&g_cnt[d.x], 1);
    int p1 = atomicAdd(&g_cnt[d.y], 1);
    int p2 = atomicAdd(&g_cnt[d.z], 1);
    int p3 = atomicAdd(&g_cnt[d.w], 1);
    if (p0 < CAP) g_bkt[(size_t)d.x * CAP + p0] = s.x;
    if (p1 < CAP) g_bkt[(size_t)d.y * CAP + p1] = s.y;
    if (p2 < CAP) g_bkt[(size_t)d.z * CAP + p2] = s.z;
    if (p3 < CAP) g_bkt[(size_t)d.w * CAP + p3] = s.w;
}

// K2b: dinv lookup table (counts final after k_fill)
__global__ void k_dinv(int n) {
    int i = blockIdx.x * blockDim.x + threadIdx.x;
    if (i < n) g_dinv[i] = rsqrtf((float)g_cnt[i] + 1.0f);
}

// ---------------------------------------------------------------------------
// K3: Gather-aggregate + dropout-mask gen + tf32 convert. One warp per node.
// NO shuffles (R11 lesson: gather was SHFL/issue-bound, not L2-bound).
// Edge indices read via warp-uniform int4 LDG (1 wavefront), neighbor norms
// via warp-uniform g_dinv lookup.
// ---------------------------------------------------------------------------
__global__ __launch_bounds__(256)
void k_gather(const float* __restrict__ x, int n) {
    int wid  = blockIdx.x * 8 + (threadIdx.x >> 5);
    int lane = threadIdx.x & 31;
    if (wid >= n) return;

    int c = g_cnt[wid];
    if (c > CAP) c = CAP;
    float dv = g_dinv[wid];

    float4 acc = *(const float4*)&x[(size_t)wid * DIM + lane * 4];
    acc.x *= dv; acc.y *= dv; acc.z *= dv; acc.w *= dv;

    uint32_t bctr = (uint32_t)wid * DIM + lane;
    uint32_t m0 = __ballot_sync(0xffffffffu, !(threefry_bits(bctr +  0) >> 31));
    uint32_t m1 = __ballot_sync(0xffffffffu, !(threefry_bits(bctr + 32) >> 31));
    uint32_t m2 = __ballot_sync(0xffffffffu, !(threefry_bits(bctr + 64) >> 31));
    uint32_t m3 = __ballot_sync(0xffffffffu, !(threefry_bits(bctr + 96) >> 31));
    if (lane == 0) g_mask[wid] = make_uint4(m0, m1, m2, m3);

    const int* bkt = &g_bkt[(size_t)wid * CAP];
    const float* xl = x + lane * 4;
    int j = 0;
    for (; j + 8 <= c; j += 8) {
        int4 i0 = *(const int4*)&bkt[j];        // warp-uniform broadcast LDG
        int4 i1 = *(const int4*)&bkt[j + 4];
        float d0 = g_dinv[i0.x], d1 = g_dinv[i0.y];
        float d2 = g_dinv[i0.z], d3 = g_dinv[i0.w];
        float d4 = g_dinv[i1.x], d5 = g_dinv[i1.y];
        float d6 = g_dinv[i1.z], d7 = g_dinv[i1.w];
        float4 a0 = *(const float4*)&xl[(size_t)i0.x * DIM];
        float4 a1 = *(const float4*)&xl[(size_t)i0.y * DIM];
        float4 a2 = *(const float4*)&xl[(size_t)i0.z * DIM];
        float4 a3 = *(const float4*)&xl[(size_t)i0.w * DIM];
        float4 a4 = *(const float4*)&xl[(size_t)i1.x * DIM];
        float4 a5 = *(const float4*)&xl[(size_t)i1.y * DIM];
        float4 a6 = *(const float4*)&xl[(size_t)i1.z * DIM];
        float4 a7 = *(const float4*)&xl[(size_t)i1.w * DIM];
        acc.x = fmaf(d0, a0.x, acc.x); acc.y = fmaf(d0, a0.y, acc.y);
        acc.z = fmaf(d0, a0.z, acc.z); acc.w = fmaf(d0, a0.w, acc.w);
        acc.x = fmaf(d1, a1.x, acc.x); acc.y = fmaf(d1, a1.y, acc.y);
        acc.z = fmaf(d1, a1.z, acc.z); acc.w = fmaf(d1, a1.w, acc.w);
        acc.x = fmaf(d2, a2.x, acc.x); acc.y = fmaf(d2, a2.y, acc.y);
        acc.z = fmaf(d2, a2.z, acc.z); acc.w = fmaf(d2, a2.w, acc.w);
        acc.x = fmaf(d3, a3.x, acc.x); acc.y = fmaf(d3, a3.y, acc.y);
        acc.z = fmaf(d3, a3.z, acc.z); acc.w = fmaf(d3, a3.w, acc.w);
        acc.x = fmaf(d4, a4.x, acc.x); acc.y = fmaf(d4, a4.y, acc.y);
        acc.z = fmaf(d4, a4.z, acc.z); acc.w = fmaf(d4, a4.w, acc.w);
        acc.x = fmaf(d5, a5.x, acc.x); acc.y = fmaf(d5, a5.y, acc.y);
        acc.z = fmaf(d5, a5.z, acc.z); acc.w = fmaf(d5, a5.w, acc.w);
        acc.x = fmaf(d6, a6.x, acc.x); acc.y = fmaf(d6, a6.y, acc.y);
        acc.z = fmaf(d6, a6.z, acc.z); acc.w = fmaf(d6, a6.w, acc.w);
        acc.x = fmaf(d7, a7.x, acc.x); acc.y = fmaf(d7, a7.y, acc.y);
        acc.z = fmaf(d7, a7.z, acc.z); acc.w = fmaf(d7, a7.w, acc.w);
    }
    for (; j + 4 <= c; j += 4) {
        int4 i0 = *(const int4*)&bkt[j];
        float d0 = g_dinv[i0.x], d1 = g_dinv[i0.y];
        float d2 = g_dinv[i0.z], d3 = g_dinv[i0.w];
        float4 a0 = *(const float4*)&xl[(size_t)i0.x * DIM];
        float4 a1 = *(const float4*)&xl[(size_t)i0.y * DIM];
        float4 a2 = *(const float4*)&xl[(size_t)i0.z * DIM];
        float4 a3 = *(const float4*)&xl[(size_t)i0.w * DIM];
        acc.x = fmaf(d0, a0.x, acc.x); acc.y = fmaf(d0, a0.y, acc.y);
        acc.z = fmaf(d0, a0.z, acc.z); acc.w = fmaf(d0, a0.w, acc.w);
        acc.x = fmaf(d1, a1.x, acc.x); acc.y = fmaf(d1, a1.y, acc.y);
        acc.z = fmaf(d1, a1.z, acc.z); acc.w = fmaf(d1, a1.w, acc.w);
        acc.x = fmaf(d2, a2.x, acc.x); acc.y = fmaf(d2, a2.y, acc.y);
        acc.z = fmaf(d2, a2.z, acc.z); acc.w = fmaf(d2, a2.w, acc.w);
        acc.x = fmaf(d3, a3.x, acc.x); acc.y = fmaf(d3, a3.y, acc.y);
        acc.z = fmaf(d3, a3.z, acc.z); acc.w = fmaf(d3, a3.w, acc.w);
    }
    for (; j < c; j++) {
        int s = bkt[j];
        float dd = g_dinv[s];
        float4 a = *(const float4*)&xl[(size_t)s * DIM];
        acc.x = fmaf(dd, a.x, acc.x); acc.y = fmaf(dd, a.y, acc.y);
        acc.z = fmaf(dd, a.z, acc.z); acc.w = fmaf(dd, a.w, acc.w);
    }
    acc.x = f2tf32f(acc.x * dv); acc.y = f2tf32f(acc.y * dv);
    acc.z = f2tf32f(acc.z * dv); acc.w = f2tf32f(acc.w * dv);
    *(float4*)&g_agg[(size_t)wid * DIM + lane * 4] = acc;
}

// ---------------------------------------------------------------------------
// K4: tf32 tensor-core GEMM + bias + ReLU + dropout. (R8-proven layout)
// CTA = 64 rows x 128 cols, 8 warps (4x2), warp = 16 rows x 64 cols.
// Conflict-free fragment reads; smem 101KB -> 2 CTAs/SM.
// ---------------------------------------------------------------------------
__global__ __launch_bounds__(256, 2)
void k_gemm(const float* __restrict__ bias, float* __restrict__ out, int n)
{
    extern __shared__ uint32_t sm_u[];
    uint32_t* As = sm_u;                       // [64][APAD]
    uint32_t* Ws = sm_u + 64 * APAD;           // [128][WPAD]

    const int tid  = threadIdx.x;
    const int lane = tid & 31;
    const int wrp  = tid >> 5;
    const int base = blockIdx.x * 64;

#pragma unroll
    for (int t = 0; t < 8; t++) {
        int f = (tid + t * 256) * 4;
        int r = f >> 7, c = f & 127;
        int gr = min(base + r, n - 1);
        float4 v = *(const float4*)&g_agg[(size_t)gr * DIM + c];
        *(float4*)&As[r * APAD + c] = *(float4*)&v;
    }
#pragma unroll
    for (int t = 0; t < 16; t++) {
        int f = (tid + t * 256) * 4;
        int k = f >> 7, c = f & 127;
        float4 v = *(const float4*)&g_wtf[f];
        *(float4*)&Ws[k * WPAD + c] = v;
    }
    __syncthreads();

    const int mrow0 = (wrp >> 1) * 16;
    const int ncol0 = (wrp & 1) * 64;
    const int lr = lane >> 2;
    const int lc = lane & 3;

    float acc[8][4];
#pragma unroll
    for (int nt = 0; nt < 8; nt++)
#pragma unroll
        for (int q = 0; q < 4; q++) acc[nt][q] = 0.0f;

#pragma unroll
    for (int k0 = 0; k0 < 128; k0 += 8) {
        uint32_t a[4];
        int r = mrow0 + lr;
        a[0] = As[r * APAD + k0 + lc];
        a[1] = As[(r + 8) * APAD + k0 + lc];
        a[2] = As[r * APAD + k0 + 4 + lc];
        a[3] = As[(r + 8) * APAD + k0 + 4 + lc];
        uint32_t b[8][2];
#pragma unroll
        for (int nt = 0; nt < 8; nt++) {
            int nn = ncol0 + nt * 8 + lr;
            b[nt][0] = Ws[(k0 + lc) * WPAD + nn];
            b[nt][1] = Ws[(k0 + 4 + lc) * WPAD + nn];
        }
#pragma unroll
        for (int nt = 0; nt < 8; nt++)
            mma_tf32(acc[nt], a, b[nt]);
    }

    int r0 = base + mrow0 + lr;
    int r1 = r0 + 8;
    uint4 mk0 = (r0 < n) ? g_mask[r0] : make_uint4(0, 0, 0, 0);
    uint4 mk1 = (r1 < n) ? g_mask[r1] : make_uint4(0, 0, 0, 0);
#pragma unroll
    for (int nt = 0; nt < 8; nt++) {
        int c = ncol0 + nt * 8 + 2 * lc;
        float b0 = bias[c], b1 = bias[c + 1];
        int ws = c >> 5, sh = c & 31;
        uint32_t w0 = (ws == 0) ? mk0.x : (ws == 1) ? mk0.y : (ws == 2) ? mk0.z : mk0.w;
        uint32_t w1 = (ws == 0) ? mk1.x : (ws == 1) ? mk1.y : (ws == 2) ? mk1.z : mk1.w;
        float* cc = acc[nt];
        if (r0 < n) {
            float v0 = fmaxf(cc[0] + b0, 0.0f) * 2.0f;
            float v1 = fmaxf(cc[1] + b1, 0.0f) * 2.0f;
            v0 = ((w0 >> sh) & 1u) ? v0 : 0.0f;
            v1 = ((w0 >> (sh + 1)) & 1u) ? v1 : 0.0f;
            *(float2*)&out[(size_t)r0 * DIM + c] = make_float2(v0, v1);
        }
        if (r1 < n) {
            float v2 = fmaxf(cc[2] + b0, 0.0f) * 2.0f;
            float v3 = fmaxf(cc[3] + b1, 0.0f) * 2.0f;
            v2 = ((w1 >> sh) & 1u) ? v2 : 0.0f;
            v3 = ((w1 >> (sh + 1)) & 1u) ? v3 : 0.0f;
            *(float2*)&out[(size_t)r1 * DIM + c] = make_float2(v2, v3);
        }
    }
}

// ---------------------------------------------------------------------------
extern "C" void kernel_launch(void* const* d_in, const int* in_sizes, int n_in,
                              void* d_out, int out_size)
{
    const float* x    = (const float*)d_in[0];
    const int*   ei   = (const int*)  d_in[1];
    const float* w    = (const float*)d_in[2];
    const float* bias = (const float*)d_in[3];
    float* out = (float*)d_out;

    int n = in_sizes[0] / DIM;      // 100000
    int e = in_sizes[1] / 2;        // 1600000
    const int* srcp = ei;
    const int* dstp = ei + e;

    int n4 = (n + 3) / 4;
    int e4 = e / 4;

    const int smem_bytes = (64 * APAD + DIM * WPAD) * 4;   // 103424 B
    static bool attr_set = false;
    if (!attr_set) {
        cudaFuncSetAttribute(k_gemm, cudaFuncAttributeMaxDynamicSharedMemorySize,
                             smem_bytes);
        attr_set = true;
    }

    k_init <<<(n4 + 255) / 256, 256>>>(n4);
    k_wconv<<<16, 256>>>(w);
    k_fill <<<(e4 + 255) / 256, 256>>>(srcp, dstp, e4);
    k_dinv <<<(n + 255) / 256, 256>>>(n);
    k_gather<<<(n + 7) / 8, 256>>>(x, n);
    k_gemm <<<(n + 63) / 64, 256, smem_bytes>>>(bias, out, n);
}

// round 16
// speedup vs baseline: 1.4038x; 1.0050x over previous
#include <cuda_runtime.h>
#include <cstdint>
#include <cstring>

#define MAXN 100000
#define MAXE 1600000
#define DIM  128
#define CAP  64     // bucket capacity (Poisson(16): P(>=64) ~ 1e-30)
#define APAD 132    // A-tile smem stride: fragment banks 4*lr+lc, conflict-free
#define WPAD 136    // W smem stride: fragment banks 8*lc+lr, conflict-free

// ---------------- device scratch (no allocations allowed) -------------------
__device__ float    g_agg[(size_t)MAXN * DIM];  // aggregated feats, tf32 bits
__device__ int      g_cnt[MAXN];
__device__ int      g_bkt[(size_t)MAXN * CAP];  // per-dst source lists
__device__ float    g_dinv[MAXN];               // deg^-1/2 lookup
__device__ uint4    g_mask[MAXN];               // 128-bit dropout keep mask
__device__ uint32_t g_wtf[DIM * DIM];           // W pre-converted to tf32

// ---------------------------------------------------------------------------
// threefry2x32, JAX partitionable path (validated R1-R11)
// ---------------------------------------------------------------------------
__device__ __forceinline__ uint32_t rotl32(uint32_t v, int s) {
    return (v << s) | (v >> (32 - s));
}
__device__ __forceinline__ uint32_t threefry_bits(uint32_t ctr) {
    const uint32_t ks0 = 0u;
    const uint32_t ks1 = 42u;
    const uint32_t ks2 = 0u ^ 42u ^ 0x1BD11BDAu;
    uint32_t x0 = 0u + ks0;
    uint32_t x1 = ctr + ks1;
#define TFR(r) { x0 += x1; x1 = rotl32(x1, r); x1 ^= x0; }
    TFR(13) TFR(15) TFR(26) TFR(6)
    x0 += ks1; x1 += ks2 + 1u;
    TFR(17) TFR(29) TFR(16) TFR(24)
    x0 += ks2; x1 += ks0 + 2u;
    TFR(13) TFR(15) TFR(26) TFR(6)
    x0 += ks0; x1 += ks1 + 3u;
    TFR(17) TFR(29) TFR(16) TFR(24)
    x0 += ks1; x1 += ks2 + 4u;
    TFR(13) TFR(15) TFR(26) TFR(6)
    x0 += ks2; x1 += ks0 + 5u;
#undef TFR
    return x0 ^ x1;
}

__device__ __forceinline__ float f2tf32f(float f) {
    uint32_t r;
    asm("cvt.rna.tf32.f32 %0, %1;" : "=r"(r) : "f"(f));
    return __uint_as_float(r);
}

__device__ __forceinline__ void mma_tf32(float* c, const uint32_t* a, const uint32_t* b) {
    asm volatile(
        "mma.sync.aligned.m16n8k8.row.col.f32.tf32.tf32.f32 "
        "{%0,%1,%2,%3}, {%4,%5,%6,%7}, {%8,%9}, {%0,%1,%2,%3};"
        : "+f"(c[0]), "+f"(c[1]), "+f"(c[2]), "+f"(c[3])
        : "r"(a[0]), "r"(a[1]), "r"(a[2]), "r"(a[3]), "r"(b[0]), "r"(b[1]));
}

// ---------------------------------------------------------------------------
// K1: zero counts
// ---------------------------------------------------------------------------
__global__ void k_init(int n4) {
    int i = blockIdx.x * blockDim.x + threadIdx.x;
    if (i < n4) ((int4*)g_cnt)[i] = make_int4(0, 0, 0, 0);
}

// K1b: W -> tf32 (one-shot, 16 blocks)
__global__ void k_wconv(const float* __restrict__ w) {
    int i = (blockIdx.x * blockDim.x + threadIdx.x) * 4;
    float4 v = *(const float4*)&w[i];
    g_wtf[i + 0] = __float_as_uint(f2tf32f(v.x));
    g_wtf[i + 1] = __float_as_uint(f2tf32f(v.y));
    g_wtf[i + 2] = __float_as_uint(f2tf32f(v.z));
    g_wtf[i + 3] = __float_as_uint(f2tf32f(v.w));
}

// K2: bucket fill — 4 edges per thread (latency-bound, deep MLP)
__global__ __launch_bounds__(256)
void k_fill(const int* __restrict__ src, const int* __restrict__ dst, int e4) {
    int i = blockIdx.x * blockDim.x + threadIdx.x;
    if (i >= e4) return;
    int4 d = ((const int4*)dst)[i];
    int4 s = ((const int4*)src)[i];
    int p0 = atomicAdd(&g_cnt[d.x], 1);
    int p1 = atomicAdd(&g_cnt[d.y], 1);
    int p2 = atomicAdd(&g_cnt[d.z], 1);
    int p3 = atomicAdd(&g_cnt[d.w], 1);
    if (p0 < CAP) g_bkt[(size_t)d.x * CAP + p0] = s.x;
    if (p1 < CAP) g_bkt[(size_t)d.y * CAP + p1] = s.y;
    if (p2 < CAP) g_bkt[(size_t)d.z * CAP + p2] = s.z;
    if (p3 < CAP) g_bkt[(size_t)d.w * CAP + p3] = s.w;
}

// K2b: dinv lookup table (counts final after k_fill)
__global__ void k_dinv(int n) {
    int i = blockIdx.x * blockDim.x + threadIdx.x;
    if (i < n) g_dinv[i] = rsqrtf((float)g_cnt[i] + 1.0f);
}

// ---------------------------------------------------------------------------
// K3: Gather-aggregate + dropout-mask gen + tf32 convert. One warp per node.
// NO shuffles (R11 lesson: gather was SHFL/issue-bound, not L2-bound).
// Edge indices read via warp-uniform int4 LDG (1 wavefront), neighbor norms
// via warp-uniform g_dinv lookup.
// ---------------------------------------------------------------------------
__global__ __launch_bounds__(256)
void k_gather(const float* __restrict__ x, int n) {
    int wid  = blockIdx.x * 8 + (threadIdx.x >> 5);
    int lane = threadIdx.x & 31;
    if (wid >= n) return;

    int c = g_cnt[wid];
    if (c > CAP) c = CAP;
    float dv = g_dinv[wid];

    float4 acc = *(const float4*)&x[(size_t)wid * DIM + lane * 4];
    acc.x *= dv; acc.y *= dv; acc.z *= dv; acc.w *= dv;

    uint32_t bctr = (uint32_t)wid * DIM + lane;
    uint32_t m0 = __ballot_sync(0xffffffffu, !(threefry_bits(bctr +  0) >> 31));
    uint32_t m1 = __ballot_sync(0xffffffffu, !(threefry_bits(bctr + 32) >> 31));
    uint32_t m2 = __ballot_sync(0xffffffffu, !(threefry_bits(bctr + 64) >> 31));
    uint32_t m3 = __ballot_sync(0xffffffffu, !(threefry_bits(bctr + 96) >> 31));
    if (lane == 0) g_mask[wid] = make_uint4(m0, m1, m2, m3);

    const int* bkt = &g_bkt[(size_t)wid * CAP];
    const float* xl = x + lane * 4;
    int j = 0;
    for (; j + 8 <= c; j += 8) {
        int4 i0 = *(const int4*)&bkt[j];        // warp-uniform broadcast LDG
        int4 i1 = *(const int4*)&bkt[j + 4];
        float d0 = g_dinv[i0.x], d1 = g_dinv[i0.y];
        float d2 = g_dinv[i0.z], d3 = g_dinv[i0.w];
        float d4 = g_dinv[i1.x], d5 = g_dinv[i1.y];
        float d6 = g_dinv[i1.z], d7 = g_dinv[i1.w];
        float4 a0 = *(const float4*)&xl[(size_t)i0.x * DIM];
        float4 a1 = *(const float4*)&xl[(size_t)i0.y * DIM];
        float4 a2 = *(const float4*)&xl[(size_t)i0.z * DIM];
        float4 a3 = *(const float4*)&xl[(size_t)i0.w * DIM];
        float4 a4 = *(const float4*)&xl[(size_t)i1.x * DIM];
        float4 a5 = *(const float4*)&xl[(size_t)i1.y * DIM];
        float4 a6 = *(const float4*)&xl[(size_t)i1.z * DIM];
        float4 a7 = *(const float4*)&xl[(size_t)i1.w * DIM];
        acc.x = fmaf(d0, a0.x, acc.x); acc.y = fmaf(d0, a0.y, acc.y);
        acc.z = fmaf(d0, a0.z, acc.z); acc.w = fmaf(d0, a0.w, acc.w);
        acc.x = fmaf(d1, a1.x, acc.x); acc.y = fmaf(d1, a1.y, acc.y);
        acc.z = fmaf(d1, a1.z, acc.z); acc.w = fmaf(d1, a1.w, acc.w);
        acc.x = fmaf(d2, a2.x, acc.x); acc.y = fmaf(d2, a2.y, acc.y);
        acc.z = fmaf(d2, a2.z, acc.z); acc.w = fmaf(d2, a2.w, acc.w);
        acc.x = fmaf(d3, a3.x, acc.x); acc.y = fmaf(d3, a3.y, acc.y);
        acc.z = fmaf(d3, a3.z, acc.z); acc.w = fmaf(d3, a3.w, acc.w);
        acc.x = fmaf(d4, a4.x, acc.x); acc.y = fmaf(d4, a4.y, acc.y);
        acc.z = fmaf(d4, a4.z, acc.z); acc.w = fmaf(d4, a4.w, acc.w);
        acc.x = fmaf(d5, a5.x, acc.x); acc.y = fmaf(d5, a5.y, acc.y);
        acc.z = fmaf(d5, a5.z, acc.z); acc.w = fmaf(d5, a5.w, acc.w);
        acc.x = fmaf(d6, a6.x, acc.x); acc.y = fmaf(d6, a6.y, acc.y);
        acc.z = fmaf(d6, a6.z, acc.z); acc.w = fmaf(d6, a6.w, acc.w);
        acc.x = fmaf(d7, a7.x, acc.x); acc.y = fmaf(d7, a7.y, acc.y);
        acc.z = fmaf(d7, a7.z, acc.z); acc.w = fmaf(d7, a7.w, acc.w);
    }
    for (; j + 4 <= c; j += 4) {
        int4 i0 = *(const int4*)&bkt[j];
        float d0 = g_dinv[i0.x], d1 = g_dinv[i0.y];
        float d2 = g_dinv[i0.z], d3 = g_dinv[i0.w];
        float4 a0 = *(const float4*)&xl[(size_t)i0.x * DIM];
        float4 a1 = *(const float4*)&xl[(size_t)i0.y * DIM];
        float4 a2 = *(const float4*)&xl[(size_t)i0.z * DIM];
        float4 a3 = *(const float4*)&xl[(size_t)i0.w * DIM];
        acc.x = fmaf(d0, a0.x, acc.x); acc.y = fmaf(d0, a0.y, acc.y);
        acc.z = fmaf(d0, a0.z, acc.z); acc.w = fmaf(d0, a0.w, acc.w);
        acc.x = fmaf(d1, a1.x, acc.x); acc.y = fmaf(d1, a1.y, acc.y);
        acc.z = fmaf(d1, a1.z, acc.z); acc.w = fmaf(d1, a1.w, acc.w);
        acc.x = fmaf(d2, a2.x, acc.x); acc.y = fmaf(d2, a2.y, acc.y);
        acc.z = fmaf(d2, a2.z, acc.z); acc.w = fmaf(d2, a2.w, acc.w);
        acc.x = fmaf(d3, a3.x, acc.x); acc.y = fmaf(d3, a3.y, acc.y);
        acc.z = fmaf(d3, a3.z, acc.z); acc.w = fmaf(d3, a3.w, acc.w);
    }
    for (; j < c; j++) {
        int s = bkt[j];
        float dd = g_dinv[s];
        float4 a = *(const float4*)&xl[(size_t)s * DIM];
        acc.x = fmaf(dd, a.x, acc.x); acc.y = fmaf(dd, a.y, acc.y);
        acc.z = fmaf(dd, a.z, acc.z); acc.w = fmaf(dd, a.w, acc.w);
    }
    acc.x = f2tf32f(acc.x * dv); acc.y = f2tf32f(acc.y * dv);
    acc.z = f2tf32f(acc.z * dv); acc.w = f2tf32f(acc.w * dv);
    *(float4*)&g_agg[(size_t)wid * DIM + lane * 4] = acc;
}

// ---------------------------------------------------------------------------
// K4: tf32 tensor-core GEMM + bias + ReLU + dropout. (R8-proven layout)
// CTA = 64 rows x 128 cols, 8 warps (4x2), warp = 16 rows x 64 cols.
// Conflict-free fragment reads; smem 101KB -> 2 CTAs/SM.
// ---------------------------------------------------------------------------
__global__ __launch_bounds__(256, 2)
void k_gemm(const float* __restrict__ bias, float* __restrict__ out, int n)
{
    extern __shared__ uint32_t sm_u[];
    uint32_t* As = sm_u;                       // [64][APAD]
    uint32_t* Ws = sm_u + 64 * APAD;           // [128][WPAD]

    const int tid  = threadIdx.x;
    const int lane = tid & 31;
    const int wrp  = tid >> 5;
    const int base = blockIdx.x * 64;

#pragma unroll
    for (int t = 0; t < 8; t++) {
        int f = (tid + t * 256) * 4;
        int r = f >> 7, c = f & 127;
        int gr = min(base + r, n - 1);
        float4 v = *(const float4*)&g_agg[(size_t)gr * DIM + c];
        *(float4*)&As[r * APAD + c] = *(float4*)&v;
    }
#pragma unroll
    for (int t = 0; t < 16; t++) {
        int f = (tid + t * 256) * 4;
        int k = f >> 7, c = f & 127;
        float4 v = *(const float4*)&g_wtf[f];
        *(float4*)&Ws[k * WPAD + c] = v;
    }
    __syncthreads();

    const int mrow0 = (wrp >> 1) * 16;
    const int ncol0 = (wrp & 1) * 64;
    const int lr = lane >> 2;
    const int lc = lane & 3;

    float acc[8][4];
#pragma unroll
    for (int nt = 0; nt < 8; nt++)
#pragma unroll
        for (int q = 0; q < 4; q++) acc[nt][q] = 0.0f;

#pragma unroll
    for (int k0 = 0; k0 < 128; k0 += 8) {
        uint32_t a[4];
        int r = mrow0 + lr;
        a[0] = As[r * APAD + k0 + lc];
        a[1] = As[(r + 8) * APAD + k0 + lc];
        a[2] = As[r * APAD + k0 + 4 + lc];
        a[3] = As[(r + 8) * APAD + k0 + 4 + lc];
        uint32_t b[8][2];
#pragma unroll
        for (int nt = 0; nt < 8; nt++) {
            int nn = ncol0 + nt * 8 + lr;
            b[nt][0] = Ws[(k0 + lc) * WPAD + nn];
            b[nt][1] = Ws[(k0 + 4 + lc) * WPAD + nn];
        }
#pragma unroll
        for (int nt = 0; nt < 8; nt++)
            mma_tf32(acc[nt], a, b[nt]);
    }

    int r0 = base + mrow0 + lr;
    int r1 = r0 + 8;
    uint4 mk0 = (r0 < n) ? g_mask[r0] : make_uint4(0, 0, 0, 0);
    uint4 mk1 = (r1 < n) ? g_mask[r1] : make_uint4(0, 0, 0, 0);
#pragma unroll
    for (int nt = 0; nt < 8; nt++) {
        int c = ncol0 + nt * 8 + 2 * lc;
        float b0 = bias[c], b1 = bias[c + 1];
        int ws = c >> 5, sh = c & 31;
        uint32_t w0 = (ws == 0) ? mk0.x : (ws == 1) ? mk0.y : (ws == 2) ? mk0.z : mk0.w;
        uint32_t w1 = (ws == 0) ? mk1.x : (ws == 1) ? mk1.y : (ws == 2) ? mk1.z : mk1.w;
        float* cc = acc[nt];
        if (r0 < n) {
            float v0 = fmaxf(cc[0] + b0, 0.0f) * 2.0f;
            float v1 = fmaxf(cc[1] + b1, 0.0f) * 2.0f;
            v0 = ((w0 >> sh) & 1u) ? v0 : 0.0f;
            v1 = ((w0 >> (sh + 1)) & 1u) ? v1 : 0.0f;
            *(float2*)&out[(size_t)r0 * DIM + c] = make_float2(v0, v1);
        }
        if (r1 < n) {
            float v2 = fmaxf(cc[2] + b0, 0.0f) * 2.0f;
            float v3 = fmaxf(cc[3] + b1, 0.0f) * 2.0f;
            v2 = ((w1 >> sh) & 1u) ? v2 : 0.0f;
            v3 = ((w1 >> (sh + 1)) & 1u) ? v3 : 0.0f;
            *(float2*)&out[(size_t)r1 * DIM + c] = make_float2(v2, v3);
        }
    }
}

// ---------------------------------------------------------------------------
extern "C" void kernel_launch(void* const* d_in, const int* in_sizes, int n_in,
                              void* d_out, int out_size)
{
    const float* x    = (const float*)d_in[0];
    const int*   ei   = (const int*)  d_in[1];
    const float* w    = (const float*)d_in[2];
    const float* bias = (const float*)d_in[3];
    float* out = (float*)d_out;

    int n = in_sizes[0] / DIM;      // 100000
    int e = in_sizes[1] / 2;        // 1600000
    const int* srcp = ei;
    const int* dstp = ei + e;

    int n4 = (n + 3) / 4;
    int e4 = e / 4;

    const int smem_bytes = (64 * APAD + DIM * WPAD) * 4;   // 103424 B
    static bool attr_set = false;
    if (!attr_set) {
        cudaFuncSetAttribute(k_gemm, cudaFuncAttributeMaxDynamicSharedMemorySize,
                             smem_bytes);
        attr_set = true;
    }

    k_init <<<(n4 + 255) / 256, 256>>>(n4);
    k_wconv<<<16, 256>>>(w);
    k_fill <<<(e4 + 255) / 256, 256>>>(srcp, dstp, e4);
    k_dinv <<<(n + 255) / 256, 256>>>(n);
    k_gather<<<(n + 7) / 8, 256>>>(x, n);
    k_gemm <<<(n + 63) / 64, 256, smem_bytes>>>(bias, out, n);
}

// round 17
// speedup vs baseline: 1.4179x; 1.0101x over previous
#include <cuda_runtime.h>
#include <cstdint>
#include <cstring>

#define MAXN 100000
#define MAXE 1600000
#define DIM  128
#define CAP  64     // bucket capacity (Poisson(16): P(>=64) ~ 1e-30)
#define APAD 132    // A-tile smem stride: fragment banks 4*lr+lc, conflict-free
#define WPAD 136    // W smem stride: fragment banks 8*lc+lr, conflict-free

// ---------------- device scratch (no allocations allowed) -------------------
__device__ float    g_agg[(size_t)MAXN * DIM];  // aggregated feats, tf32 bits
__device__ int      g_cnt[MAXN];
__device__ int      g_bkt[(size_t)MAXN * CAP];  // per-dst source lists
__device__ float    g_dinv[MAXN];               // deg^-1/2 lookup
__device__ uint4    g_mask[MAXN];               // 128-bit dropout keep mask
__device__ uint32_t g_wtf[DIM * DIM];           // W pre-converted to tf32

// ---------------------------------------------------------------------------
// threefry2x32, JAX partitionable path (validated R1-R11)
// ---------------------------------------------------------------------------
__device__ __forceinline__ uint32_t rotl32(uint32_t v, int s) {
    return (v << s) | (v >> (32 - s));
}
__device__ __forceinline__ uint32_t threefry_bits(uint32_t ctr) {
    const uint32_t ks0 = 0u;
    const uint32_t ks1 = 42u;
    const uint32_t ks2 = 0u ^ 42u ^ 0x1BD11BDAu;
    uint32_t x0 = 0u + ks0;
    uint32_t x1 = ctr + ks1;
#define TFR(r) { x0 += x1; x1 = rotl32(x1, r); x1 ^= x0; }
    TFR(13) TFR(15) TFR(26) TFR(6)
    x0 += ks1; x1 += ks2 + 1u;
    TFR(17) TFR(29) TFR(16) TFR(24)
    x0 += ks2; x1 += ks0 + 2u;
    TFR(13) TFR(15) TFR(26) TFR(6)
    x0 += ks0; x1 += ks1 + 3u;
    TFR(17) TFR(29) TFR(16) TFR(24)
    x0 += ks1; x1 += ks2 + 4u;
    TFR(13) TFR(15) TFR(26) TFR(6)
    x0 += ks2; x1 += ks0 + 5u;
#undef TFR
    return x0 ^ x1;
}

__device__ __forceinline__ float f2tf32f(float f) {
    uint32_t r;
    asm("cvt.rna.tf32.f32 %0, %1;" : "=r"(r) : "f"(f));
    return __uint_as_float(r);
}

__device__ __forceinline__ void mma_tf32(float* c, const uint32_t* a, const uint32_t* b) {
    asm volatile(
        "mma.sync.aligned.m16n8k8.row.col.f32.tf32.tf32.f32 "
        "{%0,%1,%2,%3}, {%4,%5,%6,%7}, {%8,%9}, {%0,%1,%2,%3};"
        : "+f"(c[0]), "+f"(c[1]), "+f"(c[2]), "+f"(c[3])
        : "r"(a[0]), "r"(a[1]), "r"(a[2]), "r"(a[3]), "r"(b[0]), "r"(b[1]));
}

// ---------------------------------------------------------------------------
// K1: zero counts
// ---------------------------------------------------------------------------
__global__ void k_init(int n4) {
    int i = blockIdx.x * blockDim.x + threadIdx.x;
    if (i < n4) ((int4*)g_cnt)[i] = make_int4(0, 0, 0, 0);
}

// K1b: W -> tf32 (one-shot, 16 blocks)
__global__ void k_wconv(const float* __restrict__ w) {
    int i = (blockIdx.x * blockDim.x + threadIdx.x) * 4;
    float4 v = *(const float4*)&w[i];
    g_wtf[i + 0] = __float_as_uint(f2tf32f(v.x));
    g_wtf[i + 1] = __float_as_uint(f2tf32f(v.y));
    g_wtf[i + 2] = __float_as_uint(f2tf32f(v.z));
    g_wtf[i + 3] = __float_as_uint(f2tf32f(v.w));
}

// K2: bucket fill — 4 edges per thread (latency-bound, deep MLP)
__global__ __launch_bounds__(256)
void k_fill(const int* __restrict__ src, const int* __restrict__ dst, int e4) {
    int i = blockIdx.x * blockDim.x + threadIdx.x;
    if (i >= e4) return;
    int4 d = ((const int4*)dst)[i];
    int4 s = ((const int4*)src)[i];
    int p0 = atomicAdd(&g_cnt[d.x], 1);
    int p1 = atomicAdd(&g_cnt[d.y], 1);
    int p2 = atomicAdd(&g_cnt[d.z], 1);
    int p3 = atomicAdd(&g_cnt[d.w], 1);
    if (p0 < CAP) g_bkt[(size_t)d.x * CAP + p0] = s.x;
    if (p1 < CAP) g_bkt[(size_t)d.y * CAP + p1] = s.y;
    if (p2 < CAP) g_bkt[(size_t)d.z * CAP + p2] = s.z;
    if (p3 < CAP) g_bkt[(size_t)d.w * CAP + p3] = s.w;
}

// K2b: dinv lookup table (counts final after k_fill)
__global__ void k_dinv(int n) {
    int i = blockIdx.x * blockDim.x + threadIdx.x;
    if (i < n) g_dinv[i] = rsqrtf((float)g_cnt[i] + 1.0f);
}

// ---------------------------------------------------------------------------
// K3: Gather-aggregate + dropout-mask gen + tf32 convert. One warp per node.
// NO shuffles (R11 lesson: gather was SHFL/issue-bound, not L2-bound).
// Edge indices read via warp-uniform int4 LDG (1 wavefront), neighbor norms
// via warp-uniform g_dinv lookup.
// ---------------------------------------------------------------------------
__global__ __launch_bounds__(256)
void k_gather(const float* __restrict__ x, int n) {
    int wid  = blockIdx.x * 8 + (threadIdx.x >> 5);
    int lane = threadIdx.x & 31;
    if (wid >= n) return;

    int c = g_cnt[wid];
    if (c > CAP) c = CAP;
    float dv = g_dinv[wid];

    float4 acc = *(const float4*)&x[(size_t)wid * DIM + lane * 4];
    acc.x *= dv; acc.y *= dv; acc.z *= dv; acc.w *= dv;

    uint32_t bctr = (uint32_t)wid * DIM + lane;
    uint32_t m0 = __ballot_sync(0xffffffffu, !(threefry_bits(bctr +  0) >> 31));
    uint32_t m1 = __ballot_sync(0xffffffffu, !(threefry_bits(bctr + 32) >> 31));
    uint32_t m2 = __ballot_sync(0xffffffffu, !(threefry_bits(bctr + 64) >> 31));
    uint32_t m3 = __ballot_sync(0xffffffffu, !(threefry_bits(bctr + 96) >> 31));
    if (lane == 0) g_mask[wid] = make_uint4(m0, m1, m2, m3);

    const int* bkt = &g_bkt[(size_t)wid * CAP];
    const float* xl = x + lane * 4;
    int j = 0;
    for (; j + 8 <= c; j += 8) {
        int4 i0 = *(const int4*)&bkt[j];        // warp-uniform broadcast LDG
        int4 i1 = *(const int4*)&bkt[j + 4];
        float d0 = g_dinv[i0.x], d1 = g_dinv[i0.y];
        float d2 = g_dinv[i0.z], d3 = g_dinv[i0.w];
        float d4 = g_dinv[i1.x], d5 = g_dinv[i1.y];
        float d6 = g_dinv[i1.z], d7 = g_dinv[i1.w];
        float4 a0 = *(const float4*)&xl[(size_t)i0.x * DIM];
        float4 a1 = *(const float4*)&xl[(size_t)i0.y * DIM];
        float4 a2 = *(const float4*)&xl[(size_t)i0.z * DIM];
        float4 a3 = *(const float4*)&xl[(size_t)i0.w * DIM];
        float4 a4 = *(const float4*)&xl[(size_t)i1.x * DIM];
        float4 a5 = *(const float4*)&xl[(size_t)i1.y * DIM];
        float4 a6 = *(const float4*)&xl[(size_t)i1.z * DIM];
        float4 a7 = *(const float4*)&xl[(size_t)i1.w * DIM];
        acc.x = fmaf(d0, a0.x, acc.x); acc.y = fmaf(d0, a0.y, acc.y);
        acc.z = fmaf(d0, a0.z, acc.z); acc.w = fmaf(d0, a0.w, acc.w);
        acc.x = fmaf(d1, a1.x, acc.x); acc.y = fmaf(d1, a1.y, acc.y);
        acc.z = fmaf(d1, a1.z, acc.z); acc.w = fmaf(d1, a1.w, acc.w);
        acc.x = fmaf(d2, a2.x, acc.x); acc.y = fmaf(d2, a2.y, acc.y);
        acc.z = fmaf(d2, a2.z, acc.z); acc.w = fmaf(d2, a2.w, acc.w);
        acc.x = fmaf(d3, a3.x, acc.x); acc.y = fmaf(d3, a3.y, acc.y);
        acc.z = fmaf(d3, a3.z, acc.z); acc.w = fmaf(d3, a3.w, acc.w);
        acc.x = fmaf(d4, a4.x, acc.x); acc.y = fmaf(d4, a4.y, acc.y);
        acc.z = fmaf(d4, a4.z, acc.z); acc.w = fmaf(d4, a4.w, acc.w);
        acc.x = fmaf(d5, a5.x, acc.x); acc.y = fmaf(d5, a5.y, acc.y);
        acc.z = fmaf(d5, a5.z, acc.z); acc.w = fmaf(d5, a5.w, acc.w);
        acc.x = fmaf(d6, a6.x, acc.x); acc.y = fmaf(d6, a6.y, acc.y);
        acc.z = fmaf(d6, a6.z, acc.z); acc.w = fmaf(d6, a6.w, acc.w);
        acc.x = fmaf(d7, a7.x, acc.x); acc.y = fmaf(d7, a7.y, acc.y);
        acc.z = fmaf(d7, a7.z, acc.z); acc.w = fmaf(d7, a7.w, acc.w);
    }
    for (; j + 4 <= c; j += 4) {
        int4 i0 = *(const int4*)&bkt[j];
        float d0 = g_dinv[i0.x], d1 = g_dinv[i0.y];
        float d2 = g_dinv[i0.z], d3 = g_dinv[i0.w];
        float4 a0 = *(const float4*)&xl[(size_t)i0.x * DIM];
        float4 a1 = *(const float4*)&xl[(size_t)i0.y * DIM];
        float4 a2 = *(const float4*)&xl[(size_t)i0.z * DIM];
        float4 a3 = *(const float4*)&xl[(size_t)i0.w * DIM];
        acc.x = fmaf(d0, a0.x, acc.x); acc.y = fmaf(d0, a0.y, acc.y);
        acc.z = fmaf(d0, a0.z, acc.z); acc.w = fmaf(d0, a0.w, acc.w);
        acc.x = fmaf(d1, a1.x, acc.x); acc.y = fmaf(d1, a1.y, acc.y);
        acc.z = fmaf(d1, a1.z, acc.z); acc.w = fmaf(d1, a1.w, acc.w);
        acc.x = fmaf(d2, a2.x, acc.x); acc.y = fmaf(d2, a2.y, acc.y);
        acc.z = fmaf(d2, a2.z, acc.z); acc.w = fmaf(d2, a2.w, acc.w);
        acc.x = fmaf(d3, a3.x, acc.x); acc.y = fmaf(d3, a3.y, acc.y);
        acc.z = fmaf(d3, a3.z, acc.z); acc.w = fmaf(d3, a3.w, acc.w);
    }
    for (; j < c; j++) {
        int s = bkt[j];
        float dd = g_dinv[s];
        float4 a = *(const float4*)&xl[(size_t)s * DIM];
        acc.x = fmaf(dd, a.x, acc.x); acc.y = fmaf(dd, a.y, acc.y);
        acc.z = fmaf(dd, a.z, acc.z); acc.w = fmaf(dd, a.w, acc.w);
    }
    acc.x = f2tf32f(acc.x * dv); acc.y = f2tf32f(acc.y * dv);
    acc.z = f2tf32f(acc.z * dv); acc.w = f2tf32f(acc.w * dv);
    *(float4*)&g_agg[(size_t)wid * DIM + lane * 4] = acc;
}

// ---------------------------------------------------------------------------
// K4: tf32 tensor-core GEMM + bias + ReLU + dropout. (R8-proven layout)
// CTA = 64 rows x 128 cols, 8 warps (4x2), warp = 16 rows x 64 cols.
// Conflict-free fragment reads; smem 101KB -> 2 CTAs/SM.
// ---------------------------------------------------------------------------
__global__ __launch_bounds__(256, 2)
void k_gemm(const float* __restrict__ bias, float* __restrict__ out, int n)
{
    extern __shared__ uint32_t sm_u[];
    uint32_t* As = sm_u;                       // [64][APAD]
    uint32_t* Ws = sm_u + 64 * APAD;           // [128][WPAD]

    const int tid  = threadIdx.x;
    const int lane = tid & 31;
    const int wrp  = tid >> 5;
    const int base = blockIdx.x * 64;

#pragma unroll
    for (int t = 0; t < 8; t++) {
        int f = (tid + t * 256) * 4;
        int r = f >> 7, c = f & 127;
        int gr = min(base + r, n - 1);
        float4 v = *(const float4*)&g_agg[(size_t)gr * DIM + c];
        *(float4*)&As[r * APAD + c] = *(float4*)&v;
    }
#pragma unroll
    for (int t = 0; t < 16; t++) {
        int f = (tid + t * 256) * 4;
        int k = f >> 7, c = f & 127;
        float4 v = *(const float4*)&g_wtf[f];
        *(float4*)&Ws[k * WPAD + c] = v;
    }
    __syncthreads();

    const int mrow0 = (wrp >> 1) * 16;
    const int ncol0 = (wrp & 1) * 64;
    const int lr = lane >> 2;
    const int lc = lane & 3;

    float acc[8][4];
#pragma unroll
    for (int nt = 0; nt < 8; nt++)
#pragma unroll
        for (int q = 0; q < 4; q++) acc[nt][q] = 0.0f;

#pragma unroll
    for (int k0 = 0; k0 < 128; k0 += 8) {
        uint32_t a[4];
        int r = mrow0 + lr;
        a[0] = As[r * APAD + k0 + lc];
        a[1] = As[(r + 8) * APAD + k0 + lc];
        a[2] = As[r * APAD + k0 + 4 + lc];
        a[3] = As[(r + 8) * APAD + k0 + 4 + lc];
        uint32_t b[8][2];
#pragma unroll
        for (int nt = 0; nt < 8; nt++) {
            int nn = ncol0 + nt * 8 + lr;
            b[nt][0] = Ws[(k0 + lc) * WPAD + nn];
            b[nt][1] = Ws[(k0 + 4 + lc) * WPAD + nn];
        }
#pragma unroll
        for (int nt = 0; nt < 8; nt++)
            mma_tf32(acc[nt], a, b[nt]);
    }

    int r0 = base + mrow0 + lr;
    int r1 = r0 + 8;
    uint4 mk0 = (r0 < n) ? g_mask[r0] : make_uint4(0, 0, 0, 0);
    uint4 mk1 = (r1 < n) ? g_mask[r1] : make_uint4(0, 0, 0, 0);
#pragma unroll
    for (int nt = 0; nt < 8; nt++) {
        int c = ncol0 + nt * 8 + 2 * lc;
        float b0 = bias[c], b1 = bias[c + 1];
        int ws = c >> 5, sh = c & 31;
        uint32_t w0 = (ws == 0) ? mk0.x : (ws == 1) ? mk0.y : (ws == 2) ? mk0.z : mk0.w;
        uint32_t w1 = (ws == 0) ? mk1.x : (ws == 1) ? mk1.y : (ws == 2) ? mk1.z : mk1.w;
        float* cc = acc[nt];
        if (r0 < n) {
            float v0 = fmaxf(cc[0] + b0, 0.0f) * 2.0f;
            float v1 = fmaxf(cc[1] + b1, 0.0f) * 2.0f;
            v0 = ((w0 >> sh) & 1u) ? v0 : 0.0f;
            v1 = ((w0 >> (sh + 1)) & 1u) ? v1 : 0.0f;
            *(float2*)&out[(size_t)r0 * DIM + c] = make_float2(v0, v1);
        }
        if (r1 < n) {
            float v2 = fmaxf(cc[2] + b0, 0.0f) * 2.0f;
            float v3 = fmaxf(cc[3] + b1, 0.0f) * 2.0f;
            v2 = ((w1 >> sh) & 1u) ? v2 : 0.0f;
            v3 = ((w1 >> (sh + 1)) & 1u) ? v3 : 0.0f;
            *(float2*)&out[(size_t)r1 * DIM + c] = make_float2(v2, v3);
        }
    }
}

// ---------------------------------------------------------------------------
extern "C" void kernel_launch(void* const* d_in, const int* in_sizes, int n_in,
                              void* d_out, int out_size)
{
    const float* x    = (const float*)d_in[0];
    const int*   ei   = (const int*)  d_in[1];
    const float* w    = (const float*)d_in[2];
    const float* bias = (const float*)d_in[3];
    float* out = (float*)d_out;

    int n = in_sizes[0] / DIM;      // 100000
    int e = in_sizes[1] / 2;        // 1600000
    const int* srcp = ei;
    const int* dstp = ei + e;

    int n4 = (n + 3) / 4;
    int e4 = e / 4;

    const int smem_bytes = (64 * APAD + DIM * WPAD) * 4;   // 103424 B
    static bool attr_set = false;
    if (!attr_set) {
        cudaFuncSetAttribute(k_gemm, cudaFuncAttributeMaxDynamicSharedMemorySize,
                             smem_bytes);
        attr_set = true;
    }

    k_init <<<(n4 + 255) / 256, 256>>>(n4);
    k_wconv<<<16, 256>>>(w);
    k_fill <<<(e4 + 255) / 256, 256>>>(srcp, dstp, e4);
    k_dinv <<<(n + 255) / 256, 256>>>(n);
    k_gather<<<(n + 7) / 8, 256>>>(x, n);
    k_gemm <<<(n + 63) / 64, 256, smem_bytes>>>(bias, out, n);
}